// round 14
// baseline (speedup 1.0000x reference)
#include <cuda_runtime.h>
#include <math.h>

#define B_   4
#define C_   256
#define CO_  256
#define NTOT 85          // 64 (g=8) + 16 (g=4) + 4 (g=2) + 1 (g=1)
#define L3B  0
#define L2B  64
#define L1B  80
#define L0B  84
#define ROWS 32          // 1 + 4 + 8 + 19 kept rows per batch

// Output offsets (floats): (out, sparse_seq, all_coords, sparsity)
#define OFS_SPARSE   67108864ull
#define OFS_COORDS   (67108864ull + 32768ull)
#define OFS_SPARSITY (67108864ull + 32768ull + 512ull)

#define NEG_INF __int_as_float(0xff800000)

// Scratch (device globals — allocations forbidden). Cell-major for coalescing.
__device__ float g_pyr[B_][64][C_];   // level-3 pyramid
__device__ int   g_map8[B_][64];

// ---------------------------------------------------------------------------
// K1: grid max pool x -> pyr3 (g=8), all batches. One WARP per 32x32 cell.
// Triggers programmatic launch completion right after its last global write.
// ---------------------------------------------------------------------------
__global__ void __launch_bounds__(256, 8)
k_pool(const float* __restrict__ x) {
    int gy = blockIdx.x & 7;
    int bc = blockIdx.x >> 3;
    int c  = bc & 255;
    int b  = bc >> 8;

    int t    = threadIdx.x;
    int lane = t & 31;
    int gx   = t >> 5;

    const float4* base4 = reinterpret_cast<const float4*>(
        x + ((size_t)(b * 256 + c) * 256 + (size_t)gy * 32) * 256) + gx * 8;
    int r0 = lane >> 3;
    int f4 = lane & 7;

    float m = NEG_INF;
    #pragma unroll
    for (int i = 0; i < 8; i++) {
        float4 v = __ldcs(base4 + (size_t)(i * 4 + r0) * 64 + f4);
        m = fmaxf(m, fmaxf(fmaxf(v.x, v.y), fmaxf(v.z, v.w)));
    }
    #pragma unroll
    for (int o = 16; o > 0; o >>= 1)
        m = fmaxf(m, __shfl_xor_sync(0xffffffffu, m, o));
    if (lane == 0) g_pyr[b][gy * 8 + gx][c] = m;

    cudaTriggerProgrammaticLaunchCompletion();
}

// ---------------------------------------------------------------------------
// K2: prep + proj merged, 32 blocks (8 per batch). PDL secondary: prefetches
// wmat into L2 BEFORE griddepsync (overlaps pool's tail), then runs prep.
// ---------------------------------------------------------------------------
__global__ void k_prepproj(const float* __restrict__ ln_g, const float* __restrict__ ln_b,
                           const float* __restrict__ wmat, const float* __restrict__ bias,
                           float* __restrict__ dout) {
    int b  = blockIdx.x >> 3;
    int r0 = (blockIdx.x & 3) * 4 + (blockIdx.x & 4) * 4; // same as (bid&7)*4
    r0 = (blockIdx.x & 7) * 4;
    int t = threadIdx.x;
    int lane = t & 31, w = t >> 5;

    // --- P0: prefetch w into L2 (independent of pool's output) ---
    {
        float wpre = 0.f;
        #pragma unroll
        for (int i = 0; i < 8; i++)
            wpre += __ldcg(&wmat[t * 256 + i * 32]);
        asm volatile("" :: "f"(wpre));
    }

    // wait for k_pool's writes to become visible
    cudaGridDependencySynchronize();

    __shared__ float s_up[21][C_];    // levels 2/1/0, channel-major
    __shared__ float sl2[NTOT];
    __shared__ float simp2[16], simp1[4];
    __shared__ int   ssel[ROWS];
    __shared__ int   srank3[64], srank2[16], srank1[4];
    __shared__ float skf[4][C_];

    // --- phase A: upper pyramid levels into smem ---
    float v2a[16];
    #pragma unroll
    for (int u = 0; u < 16; u++) {
        int gy = u >> 2, gx = u & 3;
        int c0 = (gy * 2) * 8 + gx * 2;
        float v = fmaxf(fmaxf(g_pyr[b][c0][t],     g_pyr[b][c0 + 1][t]),
                        fmaxf(g_pyr[b][c0 + 8][t], g_pyr[b][c0 + 9][t]));
        v2a[u] = v;
        s_up[u][t] = v;
    }
    float v1a[4];
    #pragma unroll
    for (int u = 0; u < 4; u++) {
        int gy = u >> 1, gx = u & 1;
        int c0 = (gy * 2) * 4 + gx * 2;
        float v = fmaxf(fmaxf(v2a[c0], v2a[c0 + 1]), fmaxf(v2a[c0 + 4], v2a[c0 + 5]));
        v1a[u] = v;
        s_up[16 + u][t] = v;
    }
    s_up[20][t] = fmaxf(fmaxf(v1a[0], v1a[1]), fmaxf(v1a[2], v1a[3]));
    __syncthreads();

    // --- phase B: L2 norms per cell (8 warps stripe 85 cells) ---
    for (int u = w; u < NTOT; u += 8) {
        float acc = 0.f;
        #pragma unroll
        for (int i = 0; i < 8; i++) {
            int ch = lane + 32 * i;
            float v = (u < 64) ? g_pyr[b][u][ch] : s_up[u - 64][ch];
            acc = fmaf(v, v, acc);
        }
        #pragma unroll
        for (int o = 16; o > 0; o >>= 1)
            acc += __shfl_xor_sync(0xffffffffu, acc, o);
        if (lane == 0) sl2[u] = sqrtf(acc);
    }
    __syncthreads();
    if (t < 64) srank3[t] = -1;
    if (t < 16) {
        srank2[t] = -1;
        int gy = t >> 2, gx = t & 3;
        simp2[t] = fabsf(sl2[L2B + t] - sl2[(2 * gy) * 8 + 2 * gx]);
    }
    if (t < 4) {
        srank1[t] = -1;
        int gy = t >> 1, gx = t & 1;
        simp1[t] = fabsf(sl2[L1B + t] - sl2[L2B + (2 * gy) * 4 + 2 * gx]);
    }
    __syncthreads();

    // --- phase C: rank-based top-k (lax.top_k order: desc, ties->lower idx) ---
    if (t < 64) {
        float v = sl2[t];
        int rank = 0;
        #pragma unroll 16
        for (int j = 0; j < 64; j++) {
            float o = sl2[j];
            rank += (o > v) || (o == v && j < t);
        }
        if (rank < 19) {
            srank3[t] = rank;
            ssel[13 + rank] = t;
            int gy = t >> 3, gx = t & 7;
            float* cp = dout + OFS_COORDS + ((size_t)b * ROWS + 13 + rank) * 4;
            cp[0] = (gx + 0.5f) * 0.125f; cp[1] = (gy + 0.5f) * 0.125f;
            cp[2] = 0.125f; cp[3] = 0.125f;
        }
    } else if (t < 80) {
        int n = t - 64;
        float v = simp2[n];
        int rank = 0;
        #pragma unroll
        for (int j = 0; j < 16; j++) {
            float o = simp2[j];
            rank += (o > v) || (o == v && j < n);
        }
        if (rank < 8) {
            srank2[n] = rank;
            ssel[5 + rank] = L2B + n;
            int gy = n >> 2, gx = n & 3;
            float* cp = dout + OFS_COORDS + ((size_t)b * ROWS + 5 + rank) * 4;
            cp[0] = (gx + 0.5f) * 0.25f; cp[1] = (gy + 0.5f) * 0.25f;
            cp[2] = 0.25f; cp[3] = 0.25f;
        }
    } else if (t < 84) {
        int n = t - 80;
        float v = simp1[n];
        int rank = 0;
        #pragma unroll
        for (int j = 0; j < 4; j++) {
            float o = simp1[j];
            rank += (o > v) || (o == v && j < n);
        }
        srank1[n] = rank;
        ssel[1 + rank] = L1B + n;
        int gy = n >> 1, gx = n & 1;
        float* cp = dout + OFS_COORDS + ((size_t)b * ROWS + 1 + rank) * 4;
        cp[0] = (gx + 0.5f) * 0.5f; cp[1] = (gy + 0.5f) * 0.5f;
        cp[2] = 0.5f; cp[3] = 0.5f;
    } else if (t == 84) {
        ssel[0] = L0B;
        float* cp = dout + OFS_COORDS + ((size_t)b * ROWS) * 4;
        cp[0] = 0.5f; cp[1] = 0.5f; cp[2] = 1.0f; cp[3] = 1.0f;
        if (b == 0) dout[OFS_SPARSITY] = 32.0f / 65536.0f;
    }
    __syncthreads();

    // --- phase D: fine-cell -> row map (identical writes across blocks) ---
    if (t < 64) {
        int gy = t >> 3, gx = t & 7;
        int row;
        if (srank3[t] >= 0) {
            row = 13 + srank3[t];
        } else {
            int c2 = (gy >> 1) * 4 + (gx >> 1);
            if (srank2[c2] >= 0) row = 5 + srank2[c2];
            else                 row = 1 + srank1[(gy >> 2) * 2 + (gx >> 2)];
        }
        g_map8[b][t] = row;
    }

    // --- phase E: LayerNorm warp-per-row (warps 0-3; zero block syncs) ---
    __syncthreads();
    if (w < 4) {
        int row  = r0 + w;
        int cell = ssel[row];
        float vals[8];
        #pragma unroll
        for (int i = 0; i < 8; i++) {
            int ch = lane + 32 * i;
            vals[i] = (cell < 64) ? g_pyr[b][cell][ch] : s_up[cell - 64][ch];
        }
        float s = 0.f;
        #pragma unroll
        for (int i = 0; i < 8; i++) s += vals[i];
        #pragma unroll
        for (int o = 16; o > 0; o >>= 1) s += __shfl_xor_sync(0xffffffffu, s, o);
        float mean = s * (1.0f / 256.0f);
        float s2 = 0.f;
        #pragma unroll
        for (int i = 0; i < 8; i++) {
            float d = vals[i] - mean;
            s2 = fmaf(d, d, s2);
        }
        #pragma unroll
        for (int o = 16; o > 0; o >>= 1) s2 += __shfl_xor_sync(0xffffffffu, s2, o);
        float inv = rsqrtf(s2 * (1.0f / 256.0f) + 1e-5f);
        #pragma unroll
        for (int i = 0; i < 8; i++) {
            int ch = lane + 32 * i;
            skf[w][ch] = (vals[i] - mean) * inv * ln_g[ch] + ln_b[ch];
        }
    }
    __syncthreads();

    // --- phase F: GEMV for 4 rows, thread = output dim (coalesced w reads) ---
    float acc0 = bias[t], acc1 = acc0, acc2 = acc0, acc3 = acc0;
    #pragma unroll
    for (int c0 = 0; c0 < 256; c0 += 16) {
        float wv[16];
        #pragma unroll
        for (int j = 0; j < 16; j++) wv[j] = wmat[(c0 + j) * 256 + t];
        #pragma unroll
        for (int j = 0; j < 16; j++) {
            acc0 = fmaf(skf[0][c0 + j], wv[j], acc0);
            acc1 = fmaf(skf[1][c0 + j], wv[j], acc1);
            acc2 = fmaf(skf[2][c0 + j], wv[j], acc2);
            acc3 = fmaf(skf[3][c0 + j], wv[j], acc3);
        }
    }
    dout[OFS_SPARSE + ((size_t)(b * 32 + r0 + 0)) * 256 + t] = acc0;
    dout[OFS_SPARSE + ((size_t)(b * 32 + r0 + 1)) * 256 + t] = acc1;
    dout[OFS_SPARSE + ((size_t)(b * 32 + r0 + 2)) * 256 + t] = acc2;
    dout[OFS_SPARSE + ((size_t)(b * 32 + r0 + 3)) * 256 + t] = acc3;

    cudaTriggerProgrammaticLaunchCompletion();
}

// ---------------------------------------------------------------------------
// K3: dense fill, all batches. PDL secondary: index prelude overlaps
// prepproj; griddepsync before first dependent read.
// ---------------------------------------------------------------------------
__global__ void __launch_bounds__(256, 8)
k_fill(float* __restrict__ dout) {
    int y8 = blockIdx.x & 7;
    int d  = (blockIdx.x >> 3) & 255;
    int b  = blockIdx.x >> 11;
    int t  = threadIdx.x;

    float4* base = reinterpret_cast<float4*>(
        dout + ((size_t)((b * 256 + d) * 256 + y8 * 32)) * 256);

    cudaGridDependencySynchronize();

    __shared__ float sv[8];
    if (t < 8) {
        int row = g_map8[b][y8 * 8 + t];
        sv[t] = dout[OFS_SPARSE + ((size_t)(b * 32 + row)) * 256 + d];
    }
    __syncthreads();

    #pragma unroll
    for (int i = 0; i < 8; i++) {
        int ff = t + i * 256;
        float v = sv[(ff & 63) >> 3];
        __stcs(base + ff, make_float4(v, v, v, v));
    }
}

// ---------------------------------------------------------------------------
extern "C" void kernel_launch(void* const* d_in, const int* in_sizes, int n_in,
                              void* d_out, int out_size) {
    const float* x    = (const float*)d_in[0];
    const float* ln_g = (const float*)d_in[1];
    const float* ln_b = (const float*)d_in[2];
    const float* w    = (const float*)d_in[3];
    const float* bias = (const float*)d_in[4];
    float* out = (float*)d_out;
    (void)in_sizes; (void)n_in; (void)out_size;

    k_pool<<<B_ * C_ * 8, 256>>>(x);

    cudaLaunchAttribute attr[1];
    attr[0].id = cudaLaunchAttributeProgrammaticStreamSerialization;
    attr[0].val.programmaticStreamSerializationAllowed = 1;

    {
        cudaLaunchConfig_t cfg = {};
        cfg.gridDim  = dim3(B_ * 8);
        cfg.blockDim = dim3(256);
        cfg.attrs    = attr;
        cfg.numAttrs = 1;
        cudaLaunchKernelEx(&cfg, k_prepproj, ln_g, ln_b, w, bias, out);
    }
    {
        cudaLaunchConfig_t cfg = {};
        cfg.gridDim  = dim3(B_ * CO_ * 8);
        cfg.blockDim = dim3(256);
        cfg.attrs    = attr;
        cfg.numAttrs = 1;
        cudaLaunchKernelEx(&cfg, k_fill, out);
    }
}

// round 15
// speedup vs baseline: 1.0056x; 1.0056x over previous
#include <cuda_runtime.h>
#include <math.h>

#define B_   4
#define C_   256
#define CO_  256
#define NTOT 85          // 64 (g=8) + 16 (g=4) + 4 (g=2) + 1 (g=1)
#define L3B  0
#define L2B  64
#define L1B  80
#define L0B  84
#define ROWS 32          // 1 + 4 + 8 + 19 kept rows per batch

// Output offsets (floats): (out, sparse_seq, all_coords, sparsity)
#define OFS_SPARSE   67108864ull
#define OFS_COORDS   (67108864ull + 32768ull)
#define OFS_SPARSITY (67108864ull + 32768ull + 512ull)

#define NEG_INF __int_as_float(0xff800000)

// Scratch (device globals — allocations forbidden). Cell-major for coalescing.
__device__ float g_pyr[B_][64][C_];   // level-3 pyramid
__device__ int   g_map8[B_][64];

// ---------------------------------------------------------------------------
// K1: grid max pool x -> pyr3 (g=8). One WARP per TWO vertically-adjacent
// 32x32 cells: 16 streaming float4 loads issued back-to-back (MLP_p1=16),
// then two shuffle reductions. Grid = B*C*4 (gy-pairs).
// ---------------------------------------------------------------------------
__global__ void __launch_bounds__(256, 8)
k_pool(const float* __restrict__ x) {
    int p  = blockIdx.x & 3;          // gy-pair: rows gy=2p and 2p+1
    int bc = blockIdx.x >> 2;
    int c  = bc & 255;
    int b  = bc >> 8;

    int t    = threadIdx.x;
    int lane = t & 31;
    int gx   = t >> 5;

    const float4* baseA = reinterpret_cast<const float4*>(
        x + ((size_t)(b * 256 + c) * 256 + (size_t)(2 * p) * 32) * 256) + gx * 8;
    const float4* baseB = baseA + 32 * 64;   // next 32-row strip (gy = 2p+1)

    int r0 = lane >> 3;               // row offset within group of 4
    int f4 = lane & 7;                // float4 within the 32-float cell row

    // issue all 16 loads before any consumption
    float4 va[8], vb[8];
    #pragma unroll
    for (int i = 0; i < 8; i++)
        va[i] = __ldcs(baseA + (size_t)(i * 4 + r0) * 64 + f4);
    #pragma unroll
    for (int i = 0; i < 8; i++)
        vb[i] = __ldcs(baseB + (size_t)(i * 4 + r0) * 64 + f4);

    float ma = NEG_INF, mb = NEG_INF;
    #pragma unroll
    for (int i = 0; i < 8; i++) {
        ma = fmaxf(ma, fmaxf(fmaxf(va[i].x, va[i].y), fmaxf(va[i].z, va[i].w)));
        mb = fmaxf(mb, fmaxf(fmaxf(vb[i].x, vb[i].y), fmaxf(vb[i].z, vb[i].w)));
    }
    #pragma unroll
    for (int o = 16; o > 0; o >>= 1) {
        ma = fmaxf(ma, __shfl_xor_sync(0xffffffffu, ma, o));
        mb = fmaxf(mb, __shfl_xor_sync(0xffffffffu, mb, o));
    }
    if (lane == 0) {
        g_pyr[b][(2 * p) * 8 + gx][c]     = ma;
        g_pyr[b][(2 * p + 1) * 8 + gx][c] = mb;
    }
}

// ---------------------------------------------------------------------------
// K2: prep + proj merged, 32 blocks (8 per batch). w prefetched to L2 at
// entry; rank-based parallel top-k; warp-per-row LayerNorm; coalesced GEMV.
// ---------------------------------------------------------------------------
__global__ void k_prepproj(const float* __restrict__ ln_g, const float* __restrict__ ln_b,
                           const float* __restrict__ wmat, const float* __restrict__ bias,
                           float* __restrict__ dout) {
    int b  = blockIdx.x >> 3;
    int r0 = (blockIdx.x & 7) * 4;    // this block's proj rows
    int t = threadIdx.x;
    int lane = t & 31, w = t >> 5;

    // --- P0: prefetch w into L2; completes under phases A-D ---
    {
        float wpre = 0.f;
        #pragma unroll
        for (int i = 0; i < 8; i++)
            wpre += __ldcg(&wmat[t * 256 + i * 32]);
        asm volatile("" :: "f"(wpre));
    }

    __shared__ float s_up[21][C_];    // levels 2/1/0, channel-major
    __shared__ float sl2[NTOT];
    __shared__ float simp2[16], simp1[4];
    __shared__ int   ssel[ROWS];
    __shared__ int   srank3[64], srank2[16], srank1[4];
    __shared__ float skf[4][C_];

    // --- phase A: upper pyramid levels into smem ---
    float v2a[16];
    #pragma unroll
    for (int u = 0; u < 16; u++) {
        int gy = u >> 2, gx = u & 3;
        int c0 = (gy * 2) * 8 + gx * 2;
        float v = fmaxf(fmaxf(g_pyr[b][c0][t],     g_pyr[b][c0 + 1][t]),
                        fmaxf(g_pyr[b][c0 + 8][t], g_pyr[b][c0 + 9][t]));
        v2a[u] = v;
        s_up[u][t] = v;
    }
    float v1a[4];
    #pragma unroll
    for (int u = 0; u < 4; u++) {
        int gy = u >> 1, gx = u & 1;
        int c0 = (gy * 2) * 4 + gx * 2;
        float v = fmaxf(fmaxf(v2a[c0], v2a[c0 + 1]), fmaxf(v2a[c0 + 4], v2a[c0 + 5]));
        v1a[u] = v;
        s_up[16 + u][t] = v;
    }
    s_up[20][t] = fmaxf(fmaxf(v1a[0], v1a[1]), fmaxf(v1a[2], v1a[3]));
    __syncthreads();

    // --- phase B: L2 norms per cell (8 warps stripe 85 cells) ---
    for (int u = w; u < NTOT; u += 8) {
        float acc = 0.f;
        #pragma unroll
        for (int i = 0; i < 8; i++) {
            int ch = lane + 32 * i;
            float v = (u < 64) ? g_pyr[b][u][ch] : s_up[u - 64][ch];
            acc = fmaf(v, v, acc);
        }
        #pragma unroll
        for (int o = 16; o > 0; o >>= 1)
            acc += __shfl_xor_sync(0xffffffffu, acc, o);
        if (lane == 0) sl2[u] = sqrtf(acc);
    }
    __syncthreads();
    if (t < 64) srank3[t] = -1;
    if (t < 16) {
        srank2[t] = -1;
        int gy = t >> 2, gx = t & 3;
        simp2[t] = fabsf(sl2[L2B + t] - sl2[(2 * gy) * 8 + 2 * gx]);
    }
    if (t < 4) {
        srank1[t] = -1;
        int gy = t >> 1, gx = t & 1;
        simp1[t] = fabsf(sl2[L1B + t] - sl2[L2B + (2 * gy) * 4 + 2 * gx]);
    }
    __syncthreads();

    // --- phase C: rank-based top-k (lax.top_k order: desc, ties->lower idx) ---
    if (t < 64) {
        float v = sl2[t];
        int rank = 0;
        #pragma unroll 16
        for (int j = 0; j < 64; j++) {
            float o = sl2[j];
            rank += (o > v) || (o == v && j < t);
        }
        if (rank < 19) {
            srank3[t] = rank;
            ssel[13 + rank] = t;
            int gy = t >> 3, gx = t & 7;
            float* cp = dout + OFS_COORDS + ((size_t)b * ROWS + 13 + rank) * 4;
            cp[0] = (gx + 0.5f) * 0.125f; cp[1] = (gy + 0.5f) * 0.125f;
            cp[2] = 0.125f; cp[3] = 0.125f;
        }
    } else if (t < 80) {
        int n = t - 64;
        float v = simp2[n];
        int rank = 0;
        #pragma unroll
        for (int j = 0; j < 16; j++) {
            float o = simp2[j];
            rank += (o > v) || (o == v && j < n);
        }
        if (rank < 8) {
            srank2[n] = rank;
            ssel[5 + rank] = L2B + n;
            int gy = n >> 2, gx = n & 3;
            float* cp = dout + OFS_COORDS + ((size_t)b * ROWS + 5 + rank) * 4;
            cp[0] = (gx + 0.5f) * 0.25f; cp[1] = (gy + 0.5f) * 0.25f;
            cp[2] = 0.25f; cp[3] = 0.25f;
        }
    } else if (t < 84) {
        int n = t - 80;
        float v = simp1[n];
        int rank = 0;
        #pragma unroll
        for (int j = 0; j < 4; j++) {
            float o = simp1[j];
            rank += (o > v) || (o == v && j < n);
        }
        srank1[n] = rank;
        ssel[1 + rank] = L1B + n;
        int gy = n >> 1, gx = n & 1;
        float* cp = dout + OFS_COORDS + ((size_t)b * ROWS + 1 + rank) * 4;
        cp[0] = (gx + 0.5f) * 0.5f; cp[1] = (gy + 0.5f) * 0.5f;
        cp[2] = 0.5f; cp[3] = 0.5f;
    } else if (t == 84) {
        ssel[0] = L0B;
        float* cp = dout + OFS_COORDS + ((size_t)b * ROWS) * 4;
        cp[0] = 0.5f; cp[1] = 0.5f; cp[2] = 1.0f; cp[3] = 1.0f;
        if (b == 0) dout[OFS_SPARSITY] = 32.0f / 65536.0f;
    }
    __syncthreads();

    // --- phase D: fine-cell -> row map (identical writes across blocks) ---
    if (t < 64) {
        int gy = t >> 3, gx = t & 7;
        int row;
        if (srank3[t] >= 0) {
            row = 13 + srank3[t];
        } else {
            int c2 = (gy >> 1) * 4 + (gx >> 1);
            if (srank2[c2] >= 0) row = 5 + srank2[c2];
            else                 row = 1 + srank1[(gy >> 2) * 2 + (gx >> 2)];
        }
        g_map8[b][t] = row;
    }

    // --- phase E: LayerNorm warp-per-row (warps 0-3; zero block syncs) ---
    __syncthreads();
    if (w < 4) {
        int row  = r0 + w;
        int cell = ssel[row];
        float vals[8];
        #pragma unroll
        for (int i = 0; i < 8; i++) {
            int ch = lane + 32 * i;
            vals[i] = (cell < 64) ? g_pyr[b][cell][ch] : s_up[cell - 64][ch];
        }
        float s = 0.f;
        #pragma unroll
        for (int i = 0; i < 8; i++) s += vals[i];
        #pragma unroll
        for (int o = 16; o > 0; o >>= 1) s += __shfl_xor_sync(0xffffffffu, s, o);
        float mean = s * (1.0f / 256.0f);
        float s2 = 0.f;
        #pragma unroll
        for (int i = 0; i < 8; i++) {
            float d = vals[i] - mean;
            s2 = fmaf(d, d, s2);
        }
        #pragma unroll
        for (int o = 16; o > 0; o >>= 1) s2 += __shfl_xor_sync(0xffffffffu, s2, o);
        float inv = rsqrtf(s2 * (1.0f / 256.0f) + 1e-5f);
        #pragma unroll
        for (int i = 0; i < 8; i++) {
            int ch = lane + 32 * i;
            skf[w][ch] = (vals[i] - mean) * inv * ln_g[ch] + ln_b[ch];
        }
    }
    __syncthreads();

    // --- phase F: GEMV for 4 rows, thread = output dim (coalesced w reads) ---
    float acc0 = bias[t], acc1 = acc0, acc2 = acc0, acc3 = acc0;
    #pragma unroll
    for (int c0 = 0; c0 < 256; c0 += 16) {
        float wv[16];
        #pragma unroll
        for (int j = 0; j < 16; j++) wv[j] = wmat[(c0 + j) * 256 + t];
        #pragma unroll
        for (int j = 0; j < 16; j++) {
            acc0 = fmaf(skf[0][c0 + j], wv[j], acc0);
            acc1 = fmaf(skf[1][c0 + j], wv[j], acc1);
            acc2 = fmaf(skf[2][c0 + j], wv[j], acc2);
            acc3 = fmaf(skf[3][c0 + j], wv[j], acc3);
        }
    }
    dout[OFS_SPARSE + ((size_t)(b * 32 + r0 + 0)) * 256 + t] = acc0;
    dout[OFS_SPARSE + ((size_t)(b * 32 + r0 + 1)) * 256 + t] = acc1;
    dout[OFS_SPARSE + ((size_t)(b * 32 + r0 + 2)) * 256 + t] = acc2;
    dout[OFS_SPARSE + ((size_t)(b * 32 + r0 + 3)) * 256 + t] = acc3;
}

// ---------------------------------------------------------------------------
// K3: dense fill, all batches. Streaming float4 stores.
// ---------------------------------------------------------------------------
__global__ void __launch_bounds__(256, 8)
k_fill(float* __restrict__ dout) {
    int y8 = blockIdx.x & 7;
    int d  = (blockIdx.x >> 3) & 255;
    int b  = blockIdx.x >> 11;
    int t  = threadIdx.x;

    __shared__ float sv[8];
    if (t < 8) {
        int row = g_map8[b][y8 * 8 + t];
        sv[t] = dout[OFS_SPARSE + ((size_t)(b * 32 + row)) * 256 + d];
    }
    __syncthreads();

    float4* base = reinterpret_cast<float4*>(
        dout + ((size_t)((b * 256 + d) * 256 + y8 * 32)) * 256);
    #pragma unroll
    for (int i = 0; i < 8; i++) {
        int ff = t + i * 256;
        float v = sv[(ff & 63) >> 3];
        __stcs(base + ff, make_float4(v, v, v, v));
    }
}

// ---------------------------------------------------------------------------
extern "C" void kernel_launch(void* const* d_in, const int* in_sizes, int n_in,
                              void* d_out, int out_size) {
    const float* x    = (const float*)d_in[0];
    const float* ln_g = (const float*)d_in[1];
    const float* ln_b = (const float*)d_in[2];
    const float* w    = (const float*)d_in[3];
    const float* bias = (const float*)d_in[4];
    float* out = (float*)d_out;
    (void)in_sizes; (void)n_in; (void)out_size;

    k_pool<<<B_ * C_ * 4, 256>>>(x);
    k_prepproj<<<B_ * 8, 256>>>(ln_g, ln_b, w, bias, out);
    k_fill<<<B_ * CO_ * 8, 256>>>(out);
}

// round 16
// speedup vs baseline: 1.0946x; 1.0885x over previous
#include <cuda_runtime.h>
#include <math.h>

#define B_   4
#define C_   256
#define CO_  256
#define NTOT 85          // 64 (g=8) + 16 (g=4) + 4 (g=2) + 1 (g=1)
#define L3B  0
#define L2B  64
#define L1B  80
#define L0B  84
#define ROWS 32          // 1 + 4 + 8 + 19 kept rows per batch

// Output offsets (floats): (out, sparse_seq, all_coords, sparsity)
#define OFS_SPARSE   67108864ull
#define OFS_COORDS   (67108864ull + 32768ull)
#define OFS_SPARSITY (67108864ull + 32768ull + 512ull)

#define NEG_INF __int_as_float(0xff800000)

// Scratch (device globals — allocations forbidden).
__device__ float g_pyr[B_][64][C_];     // level-3 pyramid, cell-major
__device__ float g_kfn[B_][ROWS][C_];   // LayerNormed kept rows
__device__ float g_wT[CO_][C_];         // transposed weight: g_wT[d][c] = w[c][d]
__device__ int   g_map8[B_][64];        // finest-kept row per 8x8 fine cell

// ---------------------------------------------------------------------------
// K1: grid max pool (blocks 0..8191) + w transpose (blocks 8192..8255).
// Transpose blocks' scattered stores hide under pool's DRAM-bound phase.
// ---------------------------------------------------------------------------
__global__ void __launch_bounds__(256, 8)
k_pool(const float* __restrict__ x, const float* __restrict__ wmat) {
    int t = threadIdx.x;

    if (blockIdx.x >= 8192) {
        // w transpose: 64 blocks x 1024 elements, coalesced read, scatter write
        int base = (blockIdx.x - 8192) * 1024 + t * 4;
        float4 v = *reinterpret_cast<const float4*>(wmat + base);
        int c = base >> 8;
        int d = base & 255;
        g_wT[d + 0][c] = v.x;
        g_wT[d + 1][c] = v.y;
        g_wT[d + 2][c] = v.z;
        g_wT[d + 3][c] = v.w;
        return;
    }

    int gy = blockIdx.x & 7;
    int bc = blockIdx.x >> 3;
    int c  = bc & 255;
    int b  = bc >> 8;

    int lane = t & 31;
    int gx   = t >> 5;

    const float4* base4 = reinterpret_cast<const float4*>(
        x + ((size_t)(b * 256 + c) * 256 + (size_t)gy * 32) * 256) + gx * 8;
    int r0 = lane >> 3;
    int f4 = lane & 7;

    float m = NEG_INF;
    #pragma unroll
    for (int i = 0; i < 8; i++) {
        float4 v = __ldcs(base4 + (size_t)(i * 4 + r0) * 64 + f4);
        m = fmaxf(m, fmaxf(fmaxf(v.x, v.y), fmaxf(v.z, v.w)));
    }
    #pragma unroll
    for (int o = 16; o > 0; o >>= 1)
        m = fmaxf(m, __shfl_xor_sync(0xffffffffu, m, o));
    if (lane == 0) g_pyr[b][gy * 8 + gx][c] = m;
}

// ---------------------------------------------------------------------------
// K2: prep — pyramid upper levels + L2 norms + rank-based top-k + coords +
// cell->row map + LayerNorm of the 32 kept rows -> g_kfn. One block/batch.
// ---------------------------------------------------------------------------
__global__ void k_prep(const float* __restrict__ ln_g, const float* __restrict__ ln_b,
                       float* __restrict__ dout) {
    int b = blockIdx.x;
    int t = threadIdx.x;
    int lane = t & 31, w = t >> 5;

    __shared__ float s_up[21][C_];
    __shared__ float sl2[NTOT];
    __shared__ float simp2[16], simp1[4];
    __shared__ int   ssel[ROWS];
    __shared__ int   srank3[64], srank2[16], srank1[4];

    // --- phase A: upper pyramid levels into smem ---
    float v2a[16];
    #pragma unroll
    for (int u = 0; u < 16; u++) {
        int gy = u >> 2, gx = u & 3;
        int c0 = (gy * 2) * 8 + gx * 2;
        float v = fmaxf(fmaxf(g_pyr[b][c0][t],     g_pyr[b][c0 + 1][t]),
                        fmaxf(g_pyr[b][c0 + 8][t], g_pyr[b][c0 + 9][t]));
        v2a[u] = v;
        s_up[u][t] = v;
    }
    float v1a[4];
    #pragma unroll
    for (int u = 0; u < 4; u++) {
        int gy = u >> 1, gx = u & 1;
        int c0 = (gy * 2) * 4 + gx * 2;
        float v = fmaxf(fmaxf(v2a[c0], v2a[c0 + 1]), fmaxf(v2a[c0 + 4], v2a[c0 + 5]));
        v1a[u] = v;
        s_up[16 + u][t] = v;
    }
    s_up[20][t] = fmaxf(fmaxf(v1a[0], v1a[1]), fmaxf(v1a[2], v1a[3]));
    __syncthreads();

    // --- phase B: L2 norms per cell ---
    for (int u = w; u < NTOT; u += 8) {
        float acc = 0.f;
        #pragma unroll
        for (int i = 0; i < 8; i++) {
            int ch = lane + 32 * i;
            float v = (u < 64) ? g_pyr[b][u][ch] : s_up[u - 64][ch];
            acc = fmaf(v, v, acc);
        }
        #pragma unroll
        for (int o = 16; o > 0; o >>= 1)
            acc += __shfl_xor_sync(0xffffffffu, acc, o);
        if (lane == 0) sl2[u] = sqrtf(acc);
    }
    __syncthreads();
    if (t < 64) srank3[t] = -1;
    if (t < 16) {
        srank2[t] = -1;
        int gy = t >> 2, gx = t & 3;
        simp2[t] = fabsf(sl2[L2B + t] - sl2[(2 * gy) * 8 + 2 * gx]);
    }
    if (t < 4) {
        srank1[t] = -1;
        int gy = t >> 1, gx = t & 1;
        simp1[t] = fabsf(sl2[L1B + t] - sl2[L2B + (2 * gy) * 4 + 2 * gx]);
    }
    __syncthreads();

    // --- phase C: rank-based top-k (lax.top_k order: desc, ties->lower idx) ---
    if (t < 64) {
        float v = sl2[t];
        int rank = 0;
        #pragma unroll 16
        for (int j = 0; j < 64; j++) {
            float o = sl2[j];
            rank += (o > v) || (o == v && j < t);
        }
        if (rank < 19) {
            srank3[t] = rank;
            ssel[13 + rank] = t;
            int gy = t >> 3, gx = t & 7;
            float* cp = dout + OFS_COORDS + ((size_t)b * ROWS + 13 + rank) * 4;
            cp[0] = (gx + 0.5f) * 0.125f; cp[1] = (gy + 0.5f) * 0.125f;
            cp[2] = 0.125f; cp[3] = 0.125f;
        }
    } else if (t < 80) {
        int n = t - 64;
        float v = simp2[n];
        int rank = 0;
        #pragma unroll
        for (int j = 0; j < 16; j++) {
            float o = simp2[j];
            rank += (o > v) || (o == v && j < n);
        }
        if (rank < 8) {
            srank2[n] = rank;
            ssel[5 + rank] = L2B + n;
            int gy = n >> 2, gx = n & 3;
            float* cp = dout + OFS_COORDS + ((size_t)b * ROWS + 5 + rank) * 4;
            cp[0] = (gx + 0.5f) * 0.25f; cp[1] = (gy + 0.5f) * 0.25f;
            cp[2] = 0.25f; cp[3] = 0.25f;
        }
    } else if (t < 84) {
        int n = t - 80;
        float v = simp1[n];
        int rank = 0;
        #pragma unroll
        for (int j = 0; j < 4; j++) {
            float o = simp1[j];
            rank += (o > v) || (o == v && j < n);
        }
        srank1[n] = rank;
        ssel[1 + rank] = L1B + n;
        int gy = n >> 1, gx = n & 1;
        float* cp = dout + OFS_COORDS + ((size_t)b * ROWS + 1 + rank) * 4;
        cp[0] = (gx + 0.5f) * 0.5f; cp[1] = (gy + 0.5f) * 0.5f;
        cp[2] = 0.5f; cp[3] = 0.5f;
    } else if (t == 84) {
        ssel[0] = L0B;
        float* cp = dout + OFS_COORDS + ((size_t)b * ROWS) * 4;
        cp[0] = 0.5f; cp[1] = 0.5f; cp[2] = 1.0f; cp[3] = 1.0f;
        if (b == 0) dout[OFS_SPARSITY] = 32.0f / 65536.0f;
    }
    __syncthreads();

    // --- phase D: fine-cell -> row map ---
    if (t < 64) {
        int gy = t >> 3, gx = t & 7;
        int row;
        if (srank3[t] >= 0) {
            row = 13 + srank3[t];
        } else {
            int c2 = (gy >> 1) * 4 + (gx >> 1);
            if (srank2[c2] >= 0) row = 5 + srank2[c2];
            else                 row = 1 + srank1[(gy >> 2) * 2 + (gx >> 2)];
        }
        g_map8[b][t] = row;
    }
    __syncthreads();

    // --- phase E: LayerNorm, warp-per-row (4 rows per warp) -> g_kfn ---
    #pragma unroll
    for (int rr = 0; rr < 4; rr++) {
        int row  = w + rr * 8;
        int cell = ssel[row];
        float vals[8];
        #pragma unroll
        for (int i = 0; i < 8; i++) {
            int ch = lane + 32 * i;
            vals[i] = (cell < 64) ? g_pyr[b][cell][ch] : s_up[cell - 64][ch];
        }
        float s = 0.f;
        #pragma unroll
        for (int i = 0; i < 8; i++) s += vals[i];
        #pragma unroll
        for (int o = 16; o > 0; o >>= 1) s += __shfl_xor_sync(0xffffffffu, s, o);
        float mean = s * (1.0f / 256.0f);
        float s2 = 0.f;
        #pragma unroll
        for (int i = 0; i < 8; i++) {
            float d = vals[i] - mean;
            s2 = fmaf(d, d, s2);
        }
        #pragma unroll
        for (int o = 16; o > 0; o >>= 1) s2 += __shfl_xor_sync(0xffffffffu, s2, o);
        float inv = rsqrtf(s2 * (1.0f / 256.0f) + 1e-5f);
        #pragma unroll
        for (int i = 0; i < 8; i++) {
            int ch = lane + 32 * i;
            g_kfn[b][row][ch] = (vals[i] - mean) * inv * ln_g[ch] + ln_b[ch];
        }
    }
}

// ---------------------------------------------------------------------------
// K3: fill + fused projection via transposed w (all loads coalesced).
// Block (b, d, y8): wT[d] -> smem; warp j computes dot(kfn[row_j], wT[d]);
// y8==0 blocks also emit all 32 sparse_seq rows; block streams the slab.
// ---------------------------------------------------------------------------
__global__ void __launch_bounds__(256, 8)
k_fill(const float* __restrict__ bias, float* __restrict__ dout) {
    int y8 = blockIdx.x & 7;
    int d  = (blockIdx.x >> 3) & 255;
    int b  = blockIdx.x >> 11;
    int t  = threadIdx.x;
    int lane = t & 31, wj = t >> 5;

    __shared__ float s_wt[C_];
    __shared__ int   srow[8];
    __shared__ float sval[8];

    s_wt[t] = g_wT[d][t];
    if (t < 8) srow[t] = g_map8[b][y8 * 8 + t];
    __syncthreads();

    float bd = bias[d];

    // value for this warp's x-octant (both operands coalesced)
    {
        int row = srow[wj];
        float acc = 0.f;
        #pragma unroll
        for (int i = 0; i < 8; i++) {
            int c = lane + 32 * i;
            acc = fmaf(g_kfn[b][row][c], s_wt[c], acc);
        }
        #pragma unroll
        for (int o = 16; o > 0; o >>= 1) acc += __shfl_xor_sync(0xffffffffu, acc, o);
        if (lane == 0) sval[wj] = acc + bd;
    }

    // sparse_seq: the y8==0 block of each (b,d) emits all 32 rows
    if (y8 == 0) {
        #pragma unroll
        for (int rr = 0; rr < 4; rr++) {
            int row = wj + rr * 8;
            float acc = 0.f;
            #pragma unroll
            for (int i = 0; i < 8; i++) {
                int c = lane + 32 * i;
                acc = fmaf(g_kfn[b][row][c], s_wt[c], acc);
            }
            #pragma unroll
            for (int o = 16; o > 0; o >>= 1) acc += __shfl_xor_sync(0xffffffffu, acc, o);
            if (lane == 0)
                dout[OFS_SPARSE + ((size_t)(b * 32 + row)) * 256 + d] = acc + bd;
        }
    }
    __syncthreads();

    float4* base = reinterpret_cast<float4*>(
        dout + ((size_t)((b * 256 + d) * 256 + y8 * 32)) * 256);
    #pragma unroll
    for (int i = 0; i < 8; i++) {
        int ff = t + i * 256;
        float v = sval[(ff & 63) >> 3];
        __stcs(base + ff, make_float4(v, v, v, v));
    }
}

// ---------------------------------------------------------------------------
extern "C" void kernel_launch(void* const* d_in, const int* in_sizes, int n_in,
                              void* d_out, int out_size) {
    const float* x    = (const float*)d_in[0];
    const float* ln_g = (const float*)d_in[1];
    const float* ln_b = (const float*)d_in[2];
    const float* w    = (const float*)d_in[3];
    const float* bias = (const float*)d_in[4];
    float* out = (float*)d_out;
    (void)in_sizes; (void)n_in; (void)out_size;

    k_pool<<<B_ * C_ * 8 + 64, 256>>>(x, w);
    k_prep<<<B_, 256>>>(ln_g, ln_b, out);
    k_fill<<<B_ * CO_ * 8, 256>>>(bias, out);
}